// round 1
// baseline (speedup 1.0000x reference)
#include <cuda_runtime.h>
#include <math.h>

// ---------------------------------------------------------------------------
// Problem constants
// ---------------------------------------------------------------------------
#define B_     32
#define NQ_    4096
#define NK_    77
#define HEADS_ 8
#define DH_    40
#define INNER_ 320      // HEADS*DH
#define QDIM_  320
#define CDIM_  768

// Scratch (device globals: allocation-free per harness rules)
__device__ float g_q[(size_t)B_ * NQ_ * INNER_];   // 160 MB
__device__ float g_o[(size_t)B_ * NQ_ * INNER_];   // 160 MB
__device__ float g_k[(size_t)B_ * NK_ * INNER_];
__device__ float g_v[(size_t)B_ * NK_ * INNER_];

// ---------------------------------------------------------------------------
// f32x2 packed-math helpers (Blackwell FFMA2 path, PTX-only)
// ---------------------------------------------------------------------------
__device__ __forceinline__ unsigned long long pack2(float x, float y) {
    unsigned long long r;
    asm("mov.b64 %0, {%1,%2};" : "=l"(r) : "f"(x), "f"(y));
    return r;
}
__device__ __forceinline__ float2 unpack2(unsigned long long a) {
    float2 r;
    asm("mov.b64 {%0,%1}, %2;" : "=f"(r.x), "=f"(r.y) : "l"(a));
    return r;
}
__device__ __forceinline__ unsigned long long ffma2(
    unsigned long long a, unsigned long long b, unsigned long long c) {
    unsigned long long d;
    asm("fma.rn.f32x2 %0, %1, %2, %3;" : "=l"(d) : "l"(a), "l"(b), "l"(c));
    return d;
}
__device__ __forceinline__ unsigned long long fmul2(
    unsigned long long a, unsigned long long b) {
    unsigned long long d;
    asm("mul.rn.f32x2 %0, %1, %2;" : "=l"(d) : "l"(a), "l"(b));
    return d;
}

// ---------------------------------------------------------------------------
// GEMM:  C[m,n] = (sum_k A[m,k] * W[n,k] + bias[n]) * gamma[n]
//   A: [M,K] row-major,  W: [N,K] row-major (i.e. C = A @ W^T)
//   BM=128, BN=64, BK=32, 256 threads, f32x2 accumulators.
// ---------------------------------------------------------------------------
#define BM 128
#define BN 64
#define BK 32
#define PADA 4
#define PADB 4

__global__ __launch_bounds__(256)
void gemm_awt_kernel(const float* __restrict__ A,
                     const float* __restrict__ W,
                     const float* __restrict__ gamma,
                     const float* __restrict__ bias,
                     float* __restrict__ C,
                     int M, int N, int K)
{
    __shared__ float As[BK][BM + PADA];   // transposed: As[k][m]
    __shared__ float Bs[BK][BN + PADB];   // transposed: Bs[k][n]

    const int tid = threadIdx.x;
    const int m0  = blockIdx.x * BM;
    const int n0  = blockIdx.y * BN;

    // load indices
    const int lrow = tid >> 3;            // 0..31
    const int lcol = (tid & 7) * 4;       // 0,4,...,28  (k within tile)

    // compute indices
    const int tx = tid & 15;              // n quad: n = tx*4
    const int ty = tid >> 4;              // m octet: m = ty*8 + i

    unsigned long long acc[8][2];
    #pragma unroll
    for (int i = 0; i < 8; i++) { acc[i][0] = 0ULL; acc[i][1] = 0ULL; }

    const int ksteps = K / BK;
    for (int ks = 0; ks < ksteps; ks++) {
        const int k0 = ks * BK;

        // --- load A tile: 128 x 32 (4 float4 per thread), transposed store
        #pragma unroll
        for (int i = 0; i < 4; i++) {
            int m  = lrow + i * 32;
            int gm = m0 + m; if (gm > M - 1) gm = M - 1;     // clamp (safe read)
            float4 av = *(const float4*)(A + (size_t)gm * K + k0 + lcol);
            As[lcol + 0][m] = av.x;
            As[lcol + 1][m] = av.y;
            As[lcol + 2][m] = av.z;
            As[lcol + 3][m] = av.w;
        }
        // --- load B tile: 64 x 32 (2 float4 per thread), transposed store
        #pragma unroll
        for (int i = 0; i < 2; i++) {
            int n = lrow + i * 32;
            float4 wv = *(const float4*)(W + (size_t)(n0 + n) * K + k0 + lcol);
            Bs[lcol + 0][n] = wv.x;
            Bs[lcol + 1][n] = wv.y;
            Bs[lcol + 2][n] = wv.z;
            Bs[lcol + 3][n] = wv.w;
        }
        __syncthreads();

        #pragma unroll 8
        for (int kk = 0; kk < BK; kk++) {
            float4 a0 = *(const float4*)&As[kk][ty * 8];
            float4 a1 = *(const float4*)&As[kk][ty * 8 + 4];
            float4 bq = *(const float4*)&Bs[kk][tx * 4];
            unsigned long long b01 = pack2(bq.x, bq.y);
            unsigned long long b23 = pack2(bq.z, bq.w);
            unsigned long long aa[8];
            aa[0] = pack2(a0.x, a0.x); aa[1] = pack2(a0.y, a0.y);
            aa[2] = pack2(a0.z, a0.z); aa[3] = pack2(a0.w, a0.w);
            aa[4] = pack2(a1.x, a1.x); aa[5] = pack2(a1.y, a1.y);
            aa[6] = pack2(a1.z, a1.z); aa[7] = pack2(a1.w, a1.w);
            #pragma unroll
            for (int i = 0; i < 8; i++) {
                acc[i][0] = ffma2(aa[i], b01, acc[i][0]);
                acc[i][1] = ffma2(aa[i], b23, acc[i][1]);
            }
        }
        __syncthreads();
    }

    // --- epilogue: (acc + bias) * gamma
    float4 gv = *(const float4*)&gamma[n0 + tx * 4];
    float4 bv = make_float4(0.f, 0.f, 0.f, 0.f);
    if (bias) bv = *(const float4*)&bias[n0 + tx * 4];

    #pragma unroll
    for (int i = 0; i < 8; i++) {
        int m = m0 + ty * 8 + i;
        if (m < M) {
            float2 c01 = unpack2(acc[i][0]);
            float2 c23 = unpack2(acc[i][1]);
            float4 r;
            r.x = (c01.x + bv.x) * gv.x;
            r.y = (c01.y + bv.y) * gv.y;
            r.z = (c23.x + bv.z) * gv.z;
            r.w = (c23.y + bv.w) * gv.w;
            *(float4*)(C + (size_t)m * N + n0 + tx * 4) = r;
        }
    }
}

// ---------------------------------------------------------------------------
// Attention: per (b,h), thread-per-query flash-style (no max subtraction:
// scores are O(1) by construction, exp cannot overflow fp32).
//   q,o: [B, NQ, INNER]   k,v: [B, NK, INNER]
// ---------------------------------------------------------------------------
__global__ __launch_bounds__(256)
void attn_kernel(const float* __restrict__ q,
                 const float* __restrict__ k,
                 const float* __restrict__ v,
                 float* __restrict__ o)
{
    __shared__ float ks[NK_ * DH_];
    __shared__ float vs[NK_ * DH_];

    const int b = blockIdx.z;
    const int h = blockIdx.y;
    const int tid = threadIdx.x;

    // stage K/V head slices: 77*40 floats each = 770 float4 each
    for (int idx = tid; idx < NK_ * DH_ / 4; idx += 256) {
        int j  = idx / (DH_ / 4);
        int d4 = idx % (DH_ / 4);
        const float* kb = k + ((size_t)b * NK_ + j) * INNER_ + h * DH_;
        const float* vb = v + ((size_t)b * NK_ + j) * INNER_ + h * DH_;
        ((float4*)ks)[idx] = ((const float4*)kb)[d4];
        ((float4*)vs)[idx] = ((const float4*)vb)[d4];
    }
    __syncthreads();

    const int m = blockIdx.x * 256 + tid;
    const float* qr = q + ((size_t)b * NQ_ + m) * INNER_ + h * DH_;

    unsigned long long qp[20];
    #pragma unroll
    for (int t = 0; t < 10; t++) {
        float4 qv = ((const float4*)qr)[t];
        qp[2 * t]     = pack2(qv.x, qv.y);
        qp[2 * t + 1] = pack2(qv.z, qv.w);
    }

    unsigned long long op[20];
    #pragma unroll
    for (int t = 0; t < 20; t++) op[t] = 0ULL;

    float lsum = 0.f;
    const float scale = 0.15811388300841897f;  // 40^-0.5

    for (int j = 0; j < NK_; j++) {
        const float4* kp4 = (const float4*)(ks + j * DH_);
        unsigned long long acc0 = 0ULL, acc1 = 0ULL;
        #pragma unroll
        for (int t = 0; t < 10; t++) {
            float4 kv = kp4[t];
            acc0 = ffma2(qp[2 * t],     pack2(kv.x, kv.y), acc0);
            acc1 = ffma2(qp[2 * t + 1], pack2(kv.z, kv.w), acc1);
        }
        float2 s0 = unpack2(acc0);
        float2 s1 = unpack2(acc1);
        float s = (s0.x + s0.y) + (s1.x + s1.y);
        float w = __expf(s * scale);
        lsum += w;
        unsigned long long w2 = pack2(w, w);
        const float4* vp4 = (const float4*)(vs + j * DH_);
        #pragma unroll
        for (int t = 0; t < 10; t++) {
            float4 vv = vp4[t];
            op[2 * t]     = ffma2(w2, pack2(vv.x, vv.y), op[2 * t]);
            op[2 * t + 1] = ffma2(w2, pack2(vv.z, vv.w), op[2 * t + 1]);
        }
    }

    const float inv = 1.f / lsum;
    const unsigned long long inv2 = pack2(inv, inv);
    float* orow = o + ((size_t)b * NQ_ + m) * INNER_ + h * DH_;
    #pragma unroll
    for (int t = 0; t < 10; t++) {
        float2 r0 = unpack2(fmul2(op[2 * t], inv2));
        float2 r1 = unpack2(fmul2(op[2 * t + 1], inv2));
        float4 r; r.x = r0.x; r.y = r0.y; r.z = r1.x; r.w = r1.y;
        ((float4*)orow)[t] = r;
    }
}

// ---------------------------------------------------------------------------
// Launch
// ---------------------------------------------------------------------------
extern "C" void kernel_launch(void* const* d_in, const int* in_sizes, int n_in,
                              void* d_out, int out_size)
{
    (void)in_sizes; (void)n_in; (void)out_size;
    const float* x   = (const float*)d_in[0];
    const float* ctx = (const float*)d_in[1];
    const float* Wq  = (const float*)d_in[2];
    const float* Wk  = (const float*)d_in[3];
    const float* Wv  = (const float*)d_in[4];
    const float* Wo  = (const float*)d_in[5];
    const float* bo  = (const float*)d_in[6];
    const float* gq  = (const float*)d_in[7];
    const float* gk  = (const float*)d_in[8];
    const float* gv  = (const float*)d_in[9];
    const float* go  = (const float*)d_in[10];
    float* out = (float*)d_out;

    float *qp, *kp, *vp, *op;
    cudaGetSymbolAddress((void**)&qp, g_q);
    cudaGetSymbolAddress((void**)&kp, g_k);
    cudaGetSymbolAddress((void**)&vp, g_v);
    cudaGetSymbolAddress((void**)&op, g_o);

    const int Mq  = B_ * NQ_;   // 131072
    const int Mkv = B_ * NK_;   // 2464

    dim3 thr(256);
    dim3 grid_kv((Mkv + BM - 1) / BM, INNER_ / BN);   // (20, 5)
    dim3 grid_q (Mq / BM,            INNER_ / BN);    // (1024, 5)
    dim3 grid_o (Mq / BM,            QDIM_  / BN);    // (1024, 5)
    dim3 grid_at(NQ_ / 256, HEADS_, B_);              // (16, 8, 32)

    gemm_awt_kernel<<<grid_kv, thr>>>(ctx, Wk, gk, nullptr, kp, Mkv, INNER_, CDIM_);
    gemm_awt_kernel<<<grid_kv, thr>>>(ctx, Wv, gv, nullptr, vp, Mkv, INNER_, CDIM_);
    gemm_awt_kernel<<<grid_q,  thr>>>(x,   Wq, gq, nullptr, qp, Mq,  INNER_, QDIM_);
    attn_kernel    <<<grid_at, thr>>>(qp, kp, vp, op);
    gemm_awt_kernel<<<grid_o,  thr>>>(op,  Wo, go, bo,      out, Mq, QDIM_, INNER_);
}

// round 3
// speedup vs baseline: 1.8499x; 1.8499x over previous
#include <cuda_runtime.h>
#include <cuda_fp16.h>
#include <cstdint>
#include <math.h>

// ---------------------------------------------------------------------------
// Problem constants
// ---------------------------------------------------------------------------
#define B_     32
#define NQ_    4096
#define NK_    77
#define HEADS_ 8
#define DH_    40
#define INNER_ 320      // HEADS*DH
#define QDIM_  320
#define CDIM_  768

// Scratch (device globals: allocation-free per harness rules)
__device__ float  g_q [(size_t)B_ * NQ_ * INNER_];   // 160 MB fp32 (attn input)
__device__ __half g_xh[(size_t)B_ * NQ_ * QDIM_];    // 80 MB fp16 (x converted)
__device__ __half g_oh[(size_t)B_ * NQ_ * INNER_];   // 80 MB fp16 (attn output)
__device__ float  g_k [(size_t)B_ * NK_ * INNER_];
__device__ float  g_v [(size_t)B_ * NK_ * INNER_];
__device__ __half g_wqh[INNER_ * QDIM_];
__device__ __half g_woh[QDIM_ * INNER_];

// ---------------------------------------------------------------------------
// Helpers
// ---------------------------------------------------------------------------
__device__ __forceinline__ uint32_t smem_u32(const void* p) {
    uint32_t a;
    asm("{ .reg .u64 t; cvta.to.shared.u64 t, %1; cvt.u32.u64 %0, t; }"
        : "=r"(a) : "l"(p));
    return a;
}
__device__ __forceinline__ void cp16(uint32_t dst, const void* src) {
    asm volatile("cp.async.cg.shared.global [%0], [%1], 16;" :: "r"(dst), "l"(src));
}
#define CP_COMMIT() asm volatile("cp.async.commit_group;" ::: "memory")
#define CP_WAIT(N)  asm volatile("cp.async.wait_group %0;" :: "n"(N) : "memory")

__device__ __forceinline__ void ldm_x4(uint32_t* r, uint32_t addr) {
    asm volatile("ldmatrix.sync.aligned.m8n8.x4.shared.b16 {%0,%1,%2,%3}, [%4];"
        : "=r"(r[0]), "=r"(r[1]), "=r"(r[2]), "=r"(r[3]) : "r"(addr));
}
__device__ __forceinline__ void mma16816(float* c, const uint32_t* a,
                                         uint32_t b0, uint32_t b1) {
    asm volatile("mma.sync.aligned.m16n8k16.row.col.f32.f16.f16.f32 "
        "{%0,%1,%2,%3}, {%4,%5,%6,%7}, {%8,%9}, {%0,%1,%2,%3};"
        : "+f"(c[0]), "+f"(c[1]), "+f"(c[2]), "+f"(c[3])
        : "r"(a[0]), "r"(a[1]), "r"(a[2]), "r"(a[3]), "r"(b0), "r"(b1));
}

// f32x2 packed-math helpers
__device__ __forceinline__ unsigned long long pack2(float x, float y) {
    unsigned long long r;
    asm("mov.b64 %0, {%1,%2};" : "=l"(r) : "f"(x), "f"(y));
    return r;
}
__device__ __forceinline__ float2 unpack2(unsigned long long a) {
    float2 r;
    asm("mov.b64 {%0,%1}, %2;" : "=f"(r.x), "=f"(r.y) : "l"(a));
    return r;
}
__device__ __forceinline__ unsigned long long ffma2(
    unsigned long long a, unsigned long long b, unsigned long long c) {
    unsigned long long d;
    asm("fma.rn.f32x2 %0, %1, %2, %3;" : "=l"(d) : "l"(a), "l"(b), "l"(c));
    return d;
}
__device__ __forceinline__ unsigned long long fmul2(
    unsigned long long a, unsigned long long b) {
    unsigned long long d;
    asm("mul.rn.f32x2 %0, %1, %2;" : "=l"(d) : "l"(a), "l"(b));
    return d;
}

// ---------------------------------------------------------------------------
// fp32 -> fp16 conversion (elementwise, vectorized)
// ---------------------------------------------------------------------------
__global__ void f2h_kernel(const float* __restrict__ src,
                           __half* __restrict__ dst, int n4)  // n4 = n/4
{
    int stride = gridDim.x * blockDim.x;
    for (int i = blockIdx.x * blockDim.x + threadIdx.x; i < n4; i += stride) {
        float4 f = ((const float4*)src)[i];
        __half2 h0 = __floats2half2_rn(f.x, f.y);
        __half2 h1 = __floats2half2_rn(f.z, f.w);
        uint2 u;
        u.x = *(uint32_t*)&h0;
        u.y = *(uint32_t*)&h1;
        ((uint2*)dst)[i] = u;
    }
}

// ---------------------------------------------------------------------------
// HMMA fp16 GEMM:  C[m,n] = (sum_k A[m,k]*W[n,k] + bias[n]) * gamma[n]
//   A: [M,320] fp16,  W: [320,320] fp16,  C: [M,320] fp32.
//   BM=128, BN=64, BK=32, 256 threads (8 warps, 4x2), double-buffered cp.async.
// ---------------------------------------------------------------------------
#define HBM 128
#define HBN 64
#define HBK 32
#define HROW 40   // smem row stride in halves (80B: conflict-free ldmatrix, 16B-aligned)

__global__ void __launch_bounds__(256, 1)
gemm_hmma(const __half* __restrict__ A,
          const __half* __restrict__ W,
          const float* __restrict__ gamma,
          const float* __restrict__ bias,
          float* __restrict__ C)
{
    __shared__ __half As[2][HBM][HROW];
    __shared__ __half Bs[2][HBN][HROW];

    const int tid  = threadIdx.x;
    const int lane = tid & 31;
    const int w    = tid >> 5;
    const int wm   = (w >> 1) * 32;     // warp M offset (0,32,64,96)
    const int wn   = (w & 1) * 32;      // warp N offset (0,32)
    const int m0   = blockIdx.x * HBM;
    const int n0   = blockIdx.y * HBN;

    // staging indices: A chunks (512 = 128 rows x 4), B chunks (256 = 64 x 4)
    const int ar0 = tid >> 2;           // rows 0..63   (chunk tid)
    const int ar1 = (tid + 256) >> 2;   // rows 64..127
    const int akc = (tid & 3) * 8;

    float acc[2][4][4];
    #pragma unroll
    for (int mt = 0; mt < 2; mt++)
        #pragma unroll
        for (int nt = 0; nt < 4; nt++)
            #pragma unroll
            for (int i = 0; i < 4; i++) acc[mt][nt][i] = 0.f;

    // ---- stage chunk 0 ----
    {
        const int k0 = 0;
        cp16(smem_u32(&As[0][ar0][akc]), A + (size_t)(m0 + ar0) * 320 + k0 + akc);
        cp16(smem_u32(&As[0][ar1][akc]), A + (size_t)(m0 + ar1) * 320 + k0 + akc);
        cp16(smem_u32(&Bs[0][ar0][akc]), W + (size_t)(n0 + ar0) * 320 + k0 + akc);
        CP_COMMIT();
    }

    #pragma unroll 1
    for (int ks = 0; ks < 10; ks++) {
        if (ks < 9) {
            const int k0 = (ks + 1) * HBK;
            const int nb = (ks + 1) & 1;
            cp16(smem_u32(&As[nb][ar0][akc]), A + (size_t)(m0 + ar0) * 320 + k0 + akc);
            cp16(smem_u32(&As[nb][ar1][akc]), A + (size_t)(m0 + ar1) * 320 + k0 + akc);
            cp16(smem_u32(&Bs[nb][ar0][akc]), W + (size_t)(n0 + ar0) * 320 + k0 + akc);
            CP_COMMIT();
            CP_WAIT(1);
        } else {
            CP_WAIT(0);
        }
        __syncthreads();

        const int buf = ks & 1;
        #pragma unroll
        for (int kk = 0; kk < HBK; kk += 16) {
            uint32_t af[2][4], bf[2][4];
            #pragma unroll
            for (int mt = 0; mt < 2; mt++)
                ldm_x4(af[mt], smem_u32(&As[buf][wm + mt * 16 + (lane & 15)]
                                             [kk + ((lane >> 4) & 1) * 8]));
            #pragma unroll
            for (int nh = 0; nh < 2; nh++)
                ldm_x4(bf[nh], smem_u32(&Bs[buf][wn + nh * 16 + (lane & 7) + ((lane >> 4) << 3)]
                                             [kk + ((lane >> 3) & 1) * 8]));
            #pragma unroll
            for (int mt = 0; mt < 2; mt++)
                #pragma unroll
                for (int nt = 0; nt < 4; nt++)
                    mma16816(acc[mt][nt], af[mt],
                             bf[nt >> 1][(nt & 1) * 2], bf[nt >> 1][(nt & 1) * 2 + 1]);
        }
        __syncthreads();
    }

    // ---- epilogue: (acc + bias) * gamma, fp32 out ----
    #pragma unroll
    for (int nt = 0; nt < 4; nt++) {
        const int n = n0 + wn + nt * 8 + (lane & 3) * 2;
        const float g0 = __ldg(&gamma[n]);
        const float g1 = __ldg(&gamma[n + 1]);
        const float b0 = bias ? __ldg(&bias[n])     : 0.f;
        const float b1 = bias ? __ldg(&bias[n + 1]) : 0.f;
        #pragma unroll
        for (int mt = 0; mt < 2; mt++) {
            const int r0 = m0 + wm + mt * 16 + (lane >> 2);
            float2 v0, v1;
            v0.x = (acc[mt][nt][0] + b0) * g0;
            v0.y = (acc[mt][nt][1] + b1) * g1;
            v1.x = (acc[mt][nt][2] + b0) * g0;
            v1.y = (acc[mt][nt][3] + b1) * g1;
            *(float2*)(C + (size_t)r0 * 320 + n)       = v0;
            *(float2*)(C + (size_t)(r0 + 8) * 320 + n) = v1;
        }
    }
}

// ---------------------------------------------------------------------------
// fp32 FFMA2 GEMM (K/V projections, K=768, exact fp32)
// ---------------------------------------------------------------------------
#define BM 128
#define BN 64
#define BK 32
#define PADA 4
#define PADB 4

__global__ __launch_bounds__(256)
void gemm_awt_kernel(const float* __restrict__ A,
                     const float* __restrict__ W,
                     const float* __restrict__ gamma,
                     const float* __restrict__ bias,
                     float* __restrict__ C,
                     int M, int N, int K)
{
    __shared__ float As[BK][BM + PADA];
    __shared__ float Bs[BK][BN + PADB];

    const int tid = threadIdx.x;
    const int m0  = blockIdx.x * BM;
    const int n0  = blockIdx.y * BN;

    const int lrow = tid >> 3;
    const int lcol = (tid & 7) * 4;
    const int tx = tid & 15;
    const int ty = tid >> 4;

    unsigned long long acc[8][2];
    #pragma unroll
    for (int i = 0; i < 8; i++) { acc[i][0] = 0ULL; acc[i][1] = 0ULL; }

    const int ksteps = K / BK;
    for (int ks = 0; ks < ksteps; ks++) {
        const int k0 = ks * BK;
        #pragma unroll
        for (int i = 0; i < 4; i++) {
            int m  = lrow + i * 32;
            int gm = m0 + m; if (gm > M - 1) gm = M - 1;
            float4 av = *(const float4*)(A + (size_t)gm * K + k0 + lcol);
            As[lcol + 0][m] = av.x;
            As[lcol + 1][m] = av.y;
            As[lcol + 2][m] = av.z;
            As[lcol + 3][m] = av.w;
        }
        #pragma unroll
        for (int i = 0; i < 2; i++) {
            int n = lrow + i * 32;
            float4 wv = *(const float4*)(W + (size_t)(n0 + n) * K + k0 + lcol);
            Bs[lcol + 0][n] = wv.x;
            Bs[lcol + 1][n] = wv.y;
            Bs[lcol + 2][n] = wv.z;
            Bs[lcol + 3][n] = wv.w;
        }
        __syncthreads();

        #pragma unroll 8
        for (int kk = 0; kk < BK; kk++) {
            float4 a0 = *(const float4*)&As[kk][ty * 8];
            float4 a1 = *(const float4*)&As[kk][ty * 8 + 4];
            float4 bq = *(const float4*)&Bs[kk][tx * 4];
            unsigned long long b01 = pack2(bq.x, bq.y);
            unsigned long long b23 = pack2(bq.z, bq.w);
            unsigned long long aa[8];
            aa[0] = pack2(a0.x, a0.x); aa[1] = pack2(a0.y, a0.y);
            aa[2] = pack2(a0.z, a0.z); aa[3] = pack2(a0.w, a0.w);
            aa[4] = pack2(a1.x, a1.x); aa[5] = pack2(a1.y, a1.y);
            aa[6] = pack2(a1.z, a1.z); aa[7] = pack2(a1.w, a1.w);
            #pragma unroll
            for (int i = 0; i < 8; i++) {
                acc[i][0] = ffma2(aa[i], b01, acc[i][0]);
                acc[i][1] = ffma2(aa[i], b23, acc[i][1]);
            }
        }
        __syncthreads();
    }

    float4 gv = *(const float4*)&gamma[n0 + tx * 4];
    float4 bv = make_float4(0.f, 0.f, 0.f, 0.f);
    if (bias) bv = *(const float4*)&bias[n0 + tx * 4];

    #pragma unroll
    for (int i = 0; i < 8; i++) {
        int m = m0 + ty * 8 + i;
        if (m < M) {
            float2 c01 = unpack2(acc[i][0]);
            float2 c23 = unpack2(acc[i][1]);
            float4 r;
            r.x = (c01.x + bv.x) * gv.x;
            r.y = (c01.y + bv.y) * gv.y;
            r.z = (c23.x + bv.z) * gv.z;
            r.w = (c23.y + bv.w) * gv.w;
            *(float4*)(C + (size_t)m * N + n0 + tx * 4) = r;
        }
    }
}

// ---------------------------------------------------------------------------
// Attention (fp32 math; output written as fp16 for the O-projection)
// ---------------------------------------------------------------------------
__global__ __launch_bounds__(256)
void attn_kernel(const float* __restrict__ q,
                 const float* __restrict__ k,
                 const float* __restrict__ v,
                 __half* __restrict__ o)
{
    __shared__ float ks[NK_ * DH_];
    __shared__ float vs[NK_ * DH_];

    const int b = blockIdx.z;
    const int h = blockIdx.y;
    const int tid = threadIdx.x;

    for (int idx = tid; idx < NK_ * DH_ / 4; idx += 256) {
        int j  = idx / (DH_ / 4);
        int d4 = idx % (DH_ / 4);
        const float* kb = k + ((size_t)b * NK_ + j) * INNER_ + h * DH_;
        const float* vb = v + ((size_t)b * NK_ + j) * INNER_ + h * DH_;
        ((float4*)ks)[idx] = ((const float4*)kb)[d4];
        ((float4*)vs)[idx] = ((const float4*)vb)[d4];
    }
    __syncthreads();

    const int m = blockIdx.x * 256 + tid;
    const float* qr = q + ((size_t)b * NQ_ + m) * INNER_ + h * DH_;

    unsigned long long qp[20];
    #pragma unroll
    for (int t = 0; t < 10; t++) {
        float4 qv = ((const float4*)qr)[t];
        qp[2 * t]     = pack2(qv.x, qv.y);
        qp[2 * t + 1] = pack2(qv.z, qv.w);
    }

    unsigned long long op[20];
    #pragma unroll
    for (int t = 0; t < 20; t++) op[t] = 0ULL;

    float lsum = 0.f;
    const float scale = 0.15811388300841897f;

    for (int j = 0; j < NK_; j++) {
        const float4* kp4 = (const float4*)(ks + j * DH_);
        unsigned long long acc0 = 0ULL, acc1 = 0ULL;
        #pragma unroll
        for (int t = 0; t < 10; t++) {
            float4 kv = kp4[t];
            acc0 = ffma2(qp[2 * t],     pack2(kv.x, kv.y), acc0);
            acc1 = ffma2(qp[2 * t + 1], pack2(kv.z, kv.w), acc1);
        }
        float2 s0 = unpack2(acc0);
        float2 s1 = unpack2(acc1);
        float s = (s0.x + s0.y) + (s1.x + s1.y);
        float w = __expf(s * scale);
        lsum += w;
        unsigned long long w2 = pack2(w, w);
        const float4* vp4 = (const float4*)(vs + j * DH_);
        #pragma unroll
        for (int t = 0; t < 10; t++) {
            float4 vv = vp4[t];
            op[2 * t]     = ffma2(w2, pack2(vv.x, vv.y), op[2 * t]);
            op[2 * t + 1] = ffma2(w2, pack2(vv.z, vv.w), op[2 * t + 1]);
        }
    }

    const float inv = 1.f / lsum;
    const unsigned long long inv2 = pack2(inv, inv);
    __half* orow = o + ((size_t)b * NQ_ + m) * INNER_ + h * DH_;
    #pragma unroll
    for (int t = 0; t < 10; t++) {
        float2 r0 = unpack2(fmul2(op[2 * t], inv2));
        float2 r1 = unpack2(fmul2(op[2 * t + 1], inv2));
        __half2 h0 = __floats2half2_rn(r0.x, r0.y);
        __half2 h1 = __floats2half2_rn(r1.x, r1.y);
        uint2 u;
        u.x = *(uint32_t*)&h0;
        u.y = *(uint32_t*)&h1;
        *(uint2*)(orow + t * 4) = u;
    }
}

// ---------------------------------------------------------------------------
// Launch
// ---------------------------------------------------------------------------
extern "C" void kernel_launch(void* const* d_in, const int* in_sizes, int n_in,
                              void* d_out, int out_size)
{
    (void)in_sizes; (void)n_in; (void)out_size;
    const float* x   = (const float*)d_in[0];
    const float* ctx = (const float*)d_in[1];
    const float* Wq  = (const float*)d_in[2];
    const float* Wk  = (const float*)d_in[3];
    const float* Wv  = (const float*)d_in[4];
    const float* Wo  = (const float*)d_in[5];
    const float* bo  = (const float*)d_in[6];
    const float* gq  = (const float*)d_in[7];
    const float* gk  = (const float*)d_in[8];
    const float* gv  = (const float*)d_in[9];
    const float* go  = (const float*)d_in[10];
    float* out = (float*)d_out;

    float  *qp, *kp, *vp;
    __half *xh, *oh, *wqh, *woh;
    cudaGetSymbolAddress((void**)&qp,  g_q);
    cudaGetSymbolAddress((void**)&kp,  g_k);
    cudaGetSymbolAddress((void**)&vp,  g_v);
    cudaGetSymbolAddress((void**)&xh,  g_xh);
    cudaGetSymbolAddress((void**)&oh,  g_oh);
    cudaGetSymbolAddress((void**)&wqh, g_wqh);
    cudaGetSymbolAddress((void**)&woh, g_woh);

    const int Mq  = B_ * NQ_;   // 131072
    const int Mkv = B_ * NK_;   // 2464

    dim3 thr(256);
    dim3 grid_kv((Mkv + BM - 1) / BM, INNER_ / BN);   // (20, 5)
    dim3 grid_h (Mq / HBM, 320 / HBN);                // (1024, 5)
    dim3 grid_at(NQ_ / 256, HEADS_, B_);              // (16, 8, 32)

    // fp32 -> fp16 conversions
    f2h_kernel<<<4096, 256>>>(x,  xh,  Mq * QDIM_ / 4);
    f2h_kernel<<<64,   256>>>(Wq, wqh, INNER_ * QDIM_ / 4);
    f2h_kernel<<<64,   256>>>(Wo, woh, QDIM_ * INNER_ / 4);

    // K/V projections: exact fp32
    gemm_awt_kernel<<<grid_kv, thr>>>(ctx, Wk, gk, nullptr, kp, Mkv, INNER_, CDIM_);
    gemm_awt_kernel<<<grid_kv, thr>>>(ctx, Wv, gv, nullptr, vp, Mkv, INNER_, CDIM_);

    // Q projection: HMMA fp16
    gemm_hmma<<<grid_h, thr>>>(xh, wqh, gq, nullptr, qp);

    // attention (fp32 math, fp16 output)
    attn_kernel<<<grid_at, thr>>>(qp, kp, vp, oh);

    // output projection: HMMA fp16 (+bias, *gamma_out)
    gemm_hmma<<<grid_h, thr>>>(oh, woh, go, bo, out);
}

// round 4
// speedup vs baseline: 3.4738x; 1.8778x over previous
#include <cuda_runtime.h>
#include <cuda_fp16.h>
#include <cstdint>
#include <math.h>

// ---------------------------------------------------------------------------
// Problem constants
// ---------------------------------------------------------------------------
#define B_     32
#define NQ_    4096
#define NK_    77
#define HEADS_ 8
#define DH_    40
#define INNER_ 320      // HEADS*DH
#define QDIM_  320
#define CDIM_  768

// Scratch (device globals: allocation-free per harness rules)
__device__ __half g_xh[(size_t)B_ * NQ_ * QDIM_];    // x fp16
__device__ __half g_ch[(size_t)B_ * NK_ * CDIM_];    // context fp16
__device__ __half g_qh[(size_t)B_ * NQ_ * INNER_];   // q fp16
__device__ __half g_oh[(size_t)B_ * NQ_ * INNER_];   // attn out fp16
__device__ __half g_kh[(size_t)B_ * NK_ * INNER_];
__device__ __half g_vh[(size_t)B_ * NK_ * INNER_];
__device__ __half g_wqh[INNER_ * QDIM_];
__device__ __half g_wkh[INNER_ * CDIM_];
__device__ __half g_wvh[INNER_ * CDIM_];
__device__ __half g_woh[QDIM_ * INNER_];

// ---------------------------------------------------------------------------
// Helpers
// ---------------------------------------------------------------------------
__device__ __forceinline__ uint32_t smem_u32(const void* p) {
    uint32_t a;
    asm("{ .reg .u64 t; cvta.to.shared.u64 t, %1; cvt.u32.u64 %0, t; }"
        : "=r"(a) : "l"(p));
    return a;
}
__device__ __forceinline__ void cp16(uint32_t dst, const void* src) {
    asm volatile("cp.async.cg.shared.global [%0], [%1], 16;" :: "r"(dst), "l"(src));
}
#define CP_COMMIT() asm volatile("cp.async.commit_group;" ::: "memory")
#define CP_WAIT(N)  asm volatile("cp.async.wait_group %0;" :: "n"(N) : "memory")

__device__ __forceinline__ void ldm_x4(uint32_t* r, uint32_t addr) {
    asm volatile("ldmatrix.sync.aligned.m8n8.x4.shared.b16 {%0,%1,%2,%3}, [%4];"
        : "=r"(r[0]), "=r"(r[1]), "=r"(r[2]), "=r"(r[3]) : "r"(addr));
}
__device__ __forceinline__ void ldm_x2(uint32_t* r, uint32_t addr) {
    asm volatile("ldmatrix.sync.aligned.m8n8.x2.shared.b16 {%0,%1}, [%2];"
        : "=r"(r[0]), "=r"(r[1]) : "r"(addr));
}
__device__ __forceinline__ void mma16816(float* c, const uint32_t* a,
                                         uint32_t b0, uint32_t b1) {
    asm volatile("mma.sync.aligned.m16n8k16.row.col.f32.f16.f16.f32 "
        "{%0,%1,%2,%3}, {%4,%5,%6,%7}, {%8,%9}, {%0,%1,%2,%3};"
        : "+f"(c[0]), "+f"(c[1]), "+f"(c[2]), "+f"(c[3])
        : "r"(a[0]), "r"(a[1]), "r"(a[2]), "r"(a[3]), "r"(b0), "r"(b1));
}
__device__ __forceinline__ unsigned f2h2(float a, float b) {
    __half2 h = __floats2half2_rn(a, b);
    return *reinterpret_cast<unsigned*>(&h);
}

// ---------------------------------------------------------------------------
// fp32 -> fp16 conversion (elementwise, vectorized)
// ---------------------------------------------------------------------------
__global__ void f2h_kernel(const float* __restrict__ src,
                           __half* __restrict__ dst, int n4)
{
    int stride = gridDim.x * blockDim.x;
    for (int i = blockIdx.x * blockDim.x + threadIdx.x; i < n4; i += stride) {
        float4 f = ((const float4*)src)[i];
        uint2 u;
        u.x = f2h2(f.x, f.y);
        u.y = f2h2(f.z, f.w);
        ((uint2*)dst)[i] = u;
    }
}

// ---------------------------------------------------------------------------
// HMMA fp16 GEMM:  C[m,n] = (sum_k A[m,k]*W[n,k] + bias[n]) * gamma[n]
//   A: [M,K] fp16, W: [320,K] fp16, C: [M,320] fp32 or fp16.
//   BM=128, BN=64, BK=32, 256 threads (8 warps, 4x2), double-buffered cp.async.
// ---------------------------------------------------------------------------
#define HBM 128
#define HBN 64
#define HBK 32
#define HROW 40   // smem row stride in halves (80B)

template<int KSTEPS, bool HALF_OUT, bool GUARD>
__global__ void __launch_bounds__(256, 1)
gemm_hmma_t(const __half* __restrict__ A,
            const __half* __restrict__ W,
            const float* __restrict__ gamma,
            const float* __restrict__ bias,
            void* __restrict__ Cv,
            int M)
{
    constexpr int KD = KSTEPS * HBK;
    __shared__ __half As[2][HBM][HROW];
    __shared__ __half Bs[2][HBN][HROW];

    const int tid  = threadIdx.x;
    const int lane = tid & 31;
    const int w    = tid >> 5;
    const int wm   = (w >> 1) * 32;
    const int wn   = (w & 1) * 32;
    const int m0   = blockIdx.x * HBM;
    const int n0   = blockIdx.y * HBN;

    const int ar0 = tid >> 2;
    const int ar1 = (tid + 256) >> 2;
    const int akc = (tid & 3) * 8;

    int gr0 = m0 + ar0, gr1 = m0 + ar1;
    if (GUARD) { gr0 = min(gr0, M - 1); gr1 = min(gr1, M - 1); }

    float acc[2][4][4];
    #pragma unroll
    for (int mt = 0; mt < 2; mt++)
        #pragma unroll
        for (int nt = 0; nt < 4; nt++)
            #pragma unroll
            for (int i = 0; i < 4; i++) acc[mt][nt][i] = 0.f;

    // stage chunk 0
    cp16(smem_u32(&As[0][ar0][akc]), A + (size_t)gr0 * KD + akc);
    cp16(smem_u32(&As[0][ar1][akc]), A + (size_t)gr1 * KD + akc);
    cp16(smem_u32(&Bs[0][ar0][akc]), W + (size_t)(n0 + ar0) * KD + akc);
    CP_COMMIT();

    #pragma unroll 1
    for (int ks = 0; ks < KSTEPS; ks++) {
        if (ks < KSTEPS - 1) {
            const int k0 = (ks + 1) * HBK;
            const int nb = (ks + 1) & 1;
            cp16(smem_u32(&As[nb][ar0][akc]), A + (size_t)gr0 * KD + k0 + akc);
            cp16(smem_u32(&As[nb][ar1][akc]), A + (size_t)gr1 * KD + k0 + akc);
            cp16(smem_u32(&Bs[nb][ar0][akc]), W + (size_t)(n0 + ar0) * KD + k0 + akc);
            CP_COMMIT();
            CP_WAIT(1);
        } else {
            CP_WAIT(0);
        }
        __syncthreads();

        const int buf = ks & 1;
        #pragma unroll
        for (int kk = 0; kk < HBK; kk += 16) {
            uint32_t af[2][4], bf[2][4];
            #pragma unroll
            for (int mt = 0; mt < 2; mt++)
                ldm_x4(af[mt], smem_u32(&As[buf][wm + mt * 16 + (lane & 15)]
                                             [kk + ((lane >> 4) & 1) * 8]));
            #pragma unroll
            for (int nh = 0; nh < 2; nh++)
                ldm_x4(bf[nh], smem_u32(&Bs[buf][wn + nh * 16 + (lane & 7) + ((lane >> 4) << 3)]
                                             [kk + ((lane >> 3) & 1) * 8]));
            #pragma unroll
            for (int mt = 0; mt < 2; mt++)
                #pragma unroll
                for (int nt = 0; nt < 4; nt++)
                    mma16816(acc[mt][nt], af[mt],
                             bf[nt >> 1][(nt & 1) * 2], bf[nt >> 1][(nt & 1) * 2 + 1]);
        }
        __syncthreads();
    }

    // epilogue
    #pragma unroll
    for (int nt = 0; nt < 4; nt++) {
        const int n = n0 + wn + nt * 8 + (lane & 3) * 2;
        const float g0 = __ldg(&gamma[n]);
        const float g1 = __ldg(&gamma[n + 1]);
        const float b0 = bias ? __ldg(&bias[n])     : 0.f;
        const float b1 = bias ? __ldg(&bias[n + 1]) : 0.f;
        #pragma unroll
        for (int mt = 0; mt < 2; mt++) {
            const int r0 = m0 + wm + mt * 16 + (lane >> 2);
            float v00 = (acc[mt][nt][0] + b0) * g0;
            float v01 = (acc[mt][nt][1] + b1) * g1;
            float v10 = (acc[mt][nt][2] + b0) * g0;
            float v11 = (acc[mt][nt][3] + b1) * g1;
            if (HALF_OUT) {
                __half* C = (__half*)Cv;
                if (!GUARD || r0 < M)
                    *(uint32_t*)(C + (size_t)r0 * 320 + n) = f2h2(v00, v01);
                if (!GUARD || r0 + 8 < M)
                    *(uint32_t*)(C + (size_t)(r0 + 8) * 320 + n) = f2h2(v10, v11);
            } else {
                float* C = (float*)Cv;
                if (!GUARD || r0 < M) {
                    float2 p; p.x = v00; p.y = v01;
                    *(float2*)(C + (size_t)r0 * 320 + n) = p;
                }
                if (!GUARD || r0 + 8 < M) {
                    float2 p; p.x = v10; p.y = v11;
                    *(float2*)(C + (size_t)(r0 + 8) * 320 + n) = p;
                }
            }
        }
    }
}

// ---------------------------------------------------------------------------
// HMMA attention: per CTA 128 queries of one (b,h).  NK=77 -> padded 80.
//   S = Q K^T (fp16 mma, fp32 acc), w = exp(S*scale) masked, rowsum,
//   O = P V via in-register P->A fragment reuse, write O/rowsum fp16.
// ---------------------------------------------------------------------------
__global__ void __launch_bounds__(128)
attn_hmma(const __half* __restrict__ qh, const __half* __restrict__ kh,
          const __half* __restrict__ vh, __half* __restrict__ oh)
{
    __shared__ __half Qs[128][56];   // queries x dh(48 used)
    __shared__ __half Ks[80][56];    // keys x dh
    __shared__ __half Vt[40][88];    // dh x keys(80 used)

    const int b = blockIdx.z, h = blockIdx.y;
    const int tid = threadIdx.x, lane = tid & 31, wid = tid >> 5;
    const int m0 = blockIdx.x * 128;

    const __half* qbase = qh + ((size_t)b * NQ_ + m0) * INNER_ + h * DH_;
    const __half* kbase = kh + ((size_t)b * NK_) * INNER_ + h * DH_;
    const __half* vbase = vh + ((size_t)b * NK_) * INNER_ + h * DH_;

    // --- stage Q (640 16B chunks) ---
    #pragma unroll
    for (int i = 0; i < 5; i++) {
        int c = tid + i * 128;
        int r = c / 5, s = c % 5;
        cp16(smem_u32(&Qs[r][s * 8]), qbase + (size_t)r * INNER_ + s * 8);
    }
    // --- stage K (385 chunks) ---
    for (int c = tid; c < 385; c += 128) {
        int r = c / 5, s = c % 5;
        cp16(smem_u32(&Ks[r][s * 8]), kbase + (size_t)r * INNER_ + s * 8);
    }
    CP_COMMIT();

    // --- zero pads (disjoint from cp.async targets) ---
    const uint4 z4 = make_uint4(0, 0, 0, 0);
    *(uint4*)&Qs[tid][40] = z4;                       // Q dh pad 40-47, all 128 rows
    if (tid < 80) *(uint4*)&Ks[tid][40] = z4;         // K dh pad
    if (tid < 15) {                                   // K key-pad rows 77-79
        int r = 77 + tid / 5, s = tid % 5;
        *(uint4*)&Ks[r][s * 8] = z4;
    }
    if (tid < 120) Vt[tid / 3][77 + tid % 3] = __float2half(0.f);  // V key pad

    // --- stage V transposed (plain loads; 385 chunks) ---
    for (int c = tid; c < 385; c += 128) {
        int j = c / 5, d0 = (c % 5) * 8;
        uint4 u = *(const uint4*)(vbase + (size_t)j * INNER_ + d0);
        const __half* p = (const __half*)&u;
        #pragma unroll
        for (int i = 0; i < 8; i++) Vt[d0 + i][j] = p[i];
    }
    CP_WAIT(0);
    __syncthreads();

    // --- S = Q K^T : warp handles 32 queries (2 m16 tiles) x 80 keys ---
    const int wq = wid * 32;
    float w[2][10][4];
    #pragma unroll
    for (int mt = 0; mt < 2; mt++)
        #pragma unroll
        for (int nt = 0; nt < 10; nt++)
            #pragma unroll
            for (int i = 0; i < 4; i++) w[mt][nt][i] = 0.f;

    #pragma unroll
    for (int ksi = 0; ksi < 3; ksi++) {
        uint32_t af[2][4];
        #pragma unroll
        for (int mt = 0; mt < 2; mt++)
            ldm_x4(af[mt], smem_u32(&Qs[wq + mt * 16 + (lane & 15)]
                                       [ksi * 16 + ((lane >> 4) & 1) * 8]));
        #pragma unroll
        for (int nh = 0; nh < 5; nh++) {
            uint32_t bf[4];
            ldm_x4(bf, smem_u32(&Ks[nh * 16 + (lane & 7) + ((lane >> 4) << 3)]
                                   [ksi * 16 + ((lane >> 3) & 1) * 8]));
            #pragma unroll
            for (int mt = 0; mt < 2; mt++) {
                mma16816(w[mt][nh * 2],     af[mt], bf[0], bf[1]);
                mma16816(w[mt][nh * 2 + 1], af[mt], bf[2], bf[3]);
            }
        }
    }

    // --- softmax weights: w = exp(s*scale), mask j>=77, row sums ---
    const float scale = 0.15811388300841897f;   // 40^-0.5
    const int q2 = lane & 3;
    const bool ok0 = (72 + q2 * 2)     < 77;    // nt==9, c0/c2 col
    const bool ok1 = (72 + q2 * 2 + 1) < 77;    // nt==9, c1/c3 col
    float inv0[2], inv1[2];
    #pragma unroll
    for (int mt = 0; mt < 2; mt++) {
        float s0 = 0.f, s1 = 0.f;
        #pragma unroll
        for (int nt = 0; nt < 10; nt++) {
            float e0 = __expf(w[mt][nt][0] * scale);
            float e1 = __expf(w[mt][nt][1] * scale);
            float e2 = __expf(w[mt][nt][2] * scale);
            float e3 = __expf(w[mt][nt][3] * scale);
            if (nt == 9) {
                if (!ok0) { e0 = 0.f; e2 = 0.f; }
                if (!ok1) { e1 = 0.f; e3 = 0.f; }
            }
            w[mt][nt][0] = e0; w[mt][nt][1] = e1;
            w[mt][nt][2] = e2; w[mt][nt][3] = e3;
            s0 += e0 + e1;
            s1 += e2 + e3;
        }
        s0 += __shfl_xor_sync(0xffffffffu, s0, 1);
        s0 += __shfl_xor_sync(0xffffffffu, s0, 2);
        s1 += __shfl_xor_sync(0xffffffffu, s1, 1);
        s1 += __shfl_xor_sync(0xffffffffu, s1, 2);
        inv0[mt] = 1.f / s0;
        inv1[mt] = 1.f / s1;
    }

    // --- O = P V : P fragments built in-register from w (C->A layout reuse) ---
    float oacc[2][5][4];
    #pragma unroll
    for (int mt = 0; mt < 2; mt++)
        #pragma unroll
        for (int nt = 0; nt < 5; nt++)
            #pragma unroll
            for (int i = 0; i < 4; i++) oacc[mt][nt][i] = 0.f;

    #pragma unroll
    for (int kk = 0; kk < 5; kk++) {
        uint32_t b01[4], b23[4], b4[2];
        ldm_x4(b01, smem_u32(&Vt[(lane & 7) + ((lane >> 4) << 3)]
                                [kk * 16 + ((lane >> 3) & 1) * 8]));
        ldm_x4(b23, smem_u32(&Vt[16 + (lane & 7) + ((lane >> 4) << 3)]
                                [kk * 16 + ((lane >> 3) & 1) * 8]));
        ldm_x2(b4,  smem_u32(&Vt[32 + (lane & 7)]
                                [kk * 16 + ((lane >> 3) & 1) * 8]));
        #pragma unroll
        for (int mt = 0; mt < 2; mt++) {
            uint32_t pa[4];
            pa[0] = f2h2(w[mt][2 * kk][0],     w[mt][2 * kk][1]);
            pa[1] = f2h2(w[mt][2 * kk][2],     w[mt][2 * kk][3]);
            pa[2] = f2h2(w[mt][2 * kk + 1][0], w[mt][2 * kk + 1][1]);
            pa[3] = f2h2(w[mt][2 * kk + 1][2], w[mt][2 * kk + 1][3]);
            mma16816(oacc[mt][0], pa, b01[0], b01[1]);
            mma16816(oacc[mt][1], pa, b01[2], b01[3]);
            mma16816(oacc[mt][2], pa, b23[0], b23[1]);
            mma16816(oacc[mt][3], pa, b23[2], b23[3]);
            mma16816(oacc[mt][4], pa, b4[0],  b4[1]);
        }
    }

    // --- scale by 1/rowsum, store fp16 ---
    __half* obase = oh + ((size_t)b * NQ_ + m0) * INNER_ + h * DH_;
    #pragma unroll
    for (int mt = 0; mt < 2; mt++) {
        const int r0 = wq + mt * 16 + (lane >> 2);
        #pragma unroll
        for (int nt = 0; nt < 5; nt++) {
            const int col = nt * 8 + q2 * 2;
            *(uint32_t*)(obase + (size_t)r0 * INNER_ + col) =
                f2h2(oacc[mt][nt][0] * inv0[mt], oacc[mt][nt][1] * inv0[mt]);
            *(uint32_t*)(obase + (size_t)(r0 + 8) * INNER_ + col) =
                f2h2(oacc[mt][nt][2] * inv1[mt], oacc[mt][nt][3] * inv1[mt]);
        }
    }
}

// ---------------------------------------------------------------------------
// Launch
// ---------------------------------------------------------------------------
extern "C" void kernel_launch(void* const* d_in, const int* in_sizes, int n_in,
                              void* d_out, int out_size)
{
    (void)in_sizes; (void)n_in; (void)out_size;
    const float* x   = (const float*)d_in[0];
    const float* ctx = (const float*)d_in[1];
    const float* Wq  = (const float*)d_in[2];
    const float* Wk  = (const float*)d_in[3];
    const float* Wv  = (const float*)d_in[4];
    const float* Wo  = (const float*)d_in[5];
    const float* bo  = (const float*)d_in[6];
    const float* gq  = (const float*)d_in[7];
    const float* gk  = (const float*)d_in[8];
    const float* gv  = (const float*)d_in[9];
    const float* go  = (const float*)d_in[10];
    float* out = (float*)d_out;

    __half *xh, *ch, *qh, *oh, *kh, *vh, *wqh, *wkh, *wvh, *woh;
    cudaGetSymbolAddress((void**)&xh,  g_xh);
    cudaGetSymbolAddress((void**)&ch,  g_ch);
    cudaGetSymbolAddress((void**)&qh,  g_qh);
    cudaGetSymbolAddress((void**)&oh,  g_oh);
    cudaGetSymbolAddress((void**)&kh,  g_kh);
    cudaGetSymbolAddress((void**)&vh,  g_vh);
    cudaGetSymbolAddress((void**)&wqh, g_wqh);
    cudaGetSymbolAddress((void**)&wkh, g_wkh);
    cudaGetSymbolAddress((void**)&wvh, g_wvh);
    cudaGetSymbolAddress((void**)&woh, g_woh);

    const int Mq  = B_ * NQ_;   // 131072
    const int Mkv = B_ * NK_;   // 2464

    dim3 thr(256);
    dim3 grid_q (Mq / HBM, 320 / HBN);                   // (1024, 5)
    dim3 grid_kv((Mkv + HBM - 1) / HBM, 320 / HBN);      // (20, 5)
    dim3 grid_at(NQ_ / 128, HEADS_, B_);                 // (32, 8, 32)

    // fp32 -> fp16 conversions
    f2h_kernel<<<4096, 256>>>(x,   xh,  Mq * QDIM_ / 4);
    f2h_kernel<<<1024, 256>>>(ctx, ch,  Mkv * CDIM_ / 4);
    f2h_kernel<<<64,   256>>>(Wq,  wqh, INNER_ * QDIM_ / 4);
    f2h_kernel<<<128,  256>>>(Wk,  wkh, INNER_ * CDIM_ / 4);
    f2h_kernel<<<128,  256>>>(Wv,  wvh, INNER_ * CDIM_ / 4);
    f2h_kernel<<<64,   256>>>(Wo,  woh, QDIM_ * INNER_ / 4);

    // K/V projections (K=768, fp16 out, guarded M)
    gemm_hmma_t<24, true, true><<<grid_kv, thr>>>(ch, wkh, gk, nullptr, kh, Mkv);
    gemm_hmma_t<24, true, true><<<grid_kv, thr>>>(ch, wvh, gv, nullptr, vh, Mkv);

    // Q projection (K=320, fp16 out)
    gemm_hmma_t<10, true, false><<<grid_q, thr>>>(xh, wqh, gq, nullptr, qh, Mq);

    // attention (HMMA, fp16 in/out)
    attn_hmma<<<grid_at, 128>>>(qh, kh, vh, oh);

    // output projection (K=320, fp32 out, +bias, *gamma)
    gemm_hmma_t<10, false, false><<<grid_q, thr>>>(oh, woh, go, bo, out, Mq);
}

// round 5
// speedup vs baseline: 3.5208x; 1.0135x over previous
#include <cuda_runtime.h>
#include <cuda_fp16.h>
#include <cstdint>
#include <math.h>

// ---------------------------------------------------------------------------
// Problem constants
// ---------------------------------------------------------------------------
#define B_     32
#define NQ_    4096
#define NK_    77
#define HEADS_ 8
#define DH_    40
#define INNER_ 320      // HEADS*DH
#define QDIM_  320
#define CDIM_  768

// Scratch (device globals: allocation-free per harness rules)
__device__ __half g_xh[(size_t)B_ * NQ_ * QDIM_];    // x fp16
__device__ __half g_ch[(size_t)B_ * NK_ * CDIM_];    // context fp16
__device__ __half g_qh[(size_t)B_ * NQ_ * INNER_];   // q fp16
__device__ __half g_oh[(size_t)B_ * NQ_ * INNER_];   // attn out fp16
__device__ __half g_kh[(size_t)B_ * NK_ * INNER_];
__device__ __half g_vh[(size_t)B_ * NK_ * INNER_];
__device__ __half g_wqh[INNER_ * QDIM_];
__device__ __half g_wkh[INNER_ * CDIM_];
__device__ __half g_wvh[INNER_ * CDIM_];
__device__ __half g_woh[QDIM_ * INNER_];

// ---------------------------------------------------------------------------
// Helpers
// ---------------------------------------------------------------------------
__device__ __forceinline__ uint32_t smem_u32(const void* p) {
    uint32_t a;
    asm("{ .reg .u64 t; cvta.to.shared.u64 t, %1; cvt.u32.u64 %0, t; }"
        : "=r"(a) : "l"(p));
    return a;
}
__device__ __forceinline__ void cp16(uint32_t dst, const void* src) {
    asm volatile("cp.async.cg.shared.global [%0], [%1], 16;" :: "r"(dst), "l"(src));
}
#define CP_COMMIT() asm volatile("cp.async.commit_group;" ::: "memory")
#define CP_WAIT(N)  asm volatile("cp.async.wait_group %0;" :: "n"(N) : "memory")

__device__ __forceinline__ void ldm_x4(uint32_t* r, uint32_t addr) {
    asm volatile("ldmatrix.sync.aligned.m8n8.x4.shared.b16 {%0,%1,%2,%3}, [%4];"
        : "=r"(r[0]), "=r"(r[1]), "=r"(r[2]), "=r"(r[3]) : "r"(addr));
}
__device__ __forceinline__ void ldm_x4t(uint32_t* r, uint32_t addr) {
    asm volatile("ldmatrix.sync.aligned.m8n8.x4.trans.shared.b16 {%0,%1,%2,%3}, [%4];"
        : "=r"(r[0]), "=r"(r[1]), "=r"(r[2]), "=r"(r[3]) : "r"(addr));
}
__device__ __forceinline__ void ldm_x2t(uint32_t* r, uint32_t addr) {
    asm volatile("ldmatrix.sync.aligned.m8n8.x2.trans.shared.b16 {%0,%1}, [%2];"
        : "=r"(r[0]), "=r"(r[1]) : "r"(addr));
}
__device__ __forceinline__ void mma16816(float* c, const uint32_t* a,
                                         uint32_t b0, uint32_t b1) {
    asm volatile("mma.sync.aligned.m16n8k16.row.col.f32.f16.f16.f32 "
        "{%0,%1,%2,%3}, {%4,%5,%6,%7}, {%8,%9}, {%0,%1,%2,%3};"
        : "+f"(c[0]), "+f"(c[1]), "+f"(c[2]), "+f"(c[3])
        : "r"(a[0]), "r"(a[1]), "r"(a[2]), "r"(a[3]), "r"(b0), "r"(b1));
}
__device__ __forceinline__ unsigned f2h2(float a, float b) {
    __half2 h = __floats2half2_rn(a, b);
    return *reinterpret_cast<unsigned*>(&h);
}

// ---------------------------------------------------------------------------
// fp32 -> fp16 conversion
// ---------------------------------------------------------------------------
__global__ void f2h_kernel(const float* __restrict__ src,
                           __half* __restrict__ dst, int n4)
{
    int stride = gridDim.x * blockDim.x;
    for (int i = blockIdx.x * blockDim.x + threadIdx.x; i < n4; i += stride) {
        float4 f = ((const float4*)src)[i];
        uint2 u;
        u.x = f2h2(f.x, f.y);
        u.y = f2h2(f.z, f.w);
        ((uint2*)dst)[i] = u;
    }
}

// ---------------------------------------------------------------------------
// HMMA fp16 GEMM:  C[m,n] = (sum_k A[m,k]*W[n,k] + bias[n]) * gamma[n]
//   3-stage cp.async pipeline, one barrier per k-step, 2 CTA/SM.
// ---------------------------------------------------------------------------
#define HBM 128
#define HBN 64
#define HBK 32
#define HROW 40   // smem row stride in halves (80B)

template<int KSTEPS, bool HALF_OUT, bool GUARD>
__global__ void __launch_bounds__(256, 2)
gemm_hmma_t(const __half* __restrict__ A,
            const __half* __restrict__ W,
            const float* __restrict__ gamma,
            const float* __restrict__ bias,
            void* __restrict__ Cv,
            int M)
{
    constexpr int KD = KSTEPS * HBK;
    __shared__ __half As[3][HBM][HROW];   // 30720 B
    __shared__ __half Bs[3][HBN][HROW];   // 15360 B

    const int tid  = threadIdx.x;
    const int lane = tid & 31;
    const int w    = tid >> 5;
    const int wm   = (w >> 1) * 32;
    const int wn   = (w & 1) * 32;
    const int m0   = blockIdx.x * HBM;
    const int n0   = blockIdx.y * HBN;

    const int ar0 = tid >> 2;
    const int ar1 = (tid + 256) >> 2;
    const int akc = (tid & 3) * 8;

    int gr0 = m0 + ar0, gr1 = m0 + ar1;
    if (GUARD) { gr0 = min(gr0, M - 1); gr1 = min(gr1, M - 1); }

    const __half* pa0 = A + (size_t)gr0 * KD + akc;
    const __half* pa1 = A + (size_t)gr1 * KD + akc;
    const __half* pb0 = W + (size_t)(n0 + ar0) * KD + akc;

    float acc[2][4][4];
    #pragma unroll
    for (int mt = 0; mt < 2; mt++)
        #pragma unroll
        for (int nt = 0; nt < 4; nt++)
            #pragma unroll
            for (int i = 0; i < 4; i++) acc[mt][nt][i] = 0.f;

    // prologue: stages 0,1
    cp16(smem_u32(&As[0][ar0][akc]), pa0);
    cp16(smem_u32(&As[0][ar1][akc]), pa1);
    cp16(smem_u32(&Bs[0][ar0][akc]), pb0);
    CP_COMMIT();
    cp16(smem_u32(&As[1][ar0][akc]), pa0 + HBK);
    cp16(smem_u32(&As[1][ar1][akc]), pa1 + HBK);
    cp16(smem_u32(&Bs[1][ar0][akc]), pb0 + HBK);
    CP_COMMIT();

    int buf = 0, pbuf = 2;
    #pragma unroll 1
    for (int ks = 0; ks < KSTEPS; ks++) {
        if (ks + 1 < KSTEPS) { CP_WAIT(1); } else { CP_WAIT(0); }
        __syncthreads();
        if (ks + 2 < KSTEPS) {
            const int k0 = (ks + 2) * HBK;
            cp16(smem_u32(&As[pbuf][ar0][akc]), pa0 + k0);
            cp16(smem_u32(&As[pbuf][ar1][akc]), pa1 + k0);
            cp16(smem_u32(&Bs[pbuf][ar0][akc]), pb0 + k0);
            CP_COMMIT();
        }
        #pragma unroll
        for (int kk = 0; kk < HBK; kk += 16) {
            uint32_t af[2][4], bf[2][4];
            #pragma unroll
            for (int mt = 0; mt < 2; mt++)
                ldm_x4(af[mt], smem_u32(&As[buf][wm + mt * 16 + (lane & 15)]
                                             [kk + ((lane >> 4) & 1) * 8]));
            #pragma unroll
            for (int nh = 0; nh < 2; nh++)
                ldm_x4(bf[nh], smem_u32(&Bs[buf][wn + nh * 16 + (lane & 7) + ((lane >> 4) << 3)]
                                             [kk + ((lane >> 3) & 1) * 8]));
            #pragma unroll
            for (int mt = 0; mt < 2; mt++)
                #pragma unroll
                for (int nt = 0; nt < 4; nt++)
                    mma16816(acc[mt][nt], af[mt],
                             bf[nt >> 1][(nt & 1) * 2], bf[nt >> 1][(nt & 1) * 2 + 1]);
        }
        buf = (buf == 2) ? 0 : buf + 1;
        pbuf = (pbuf == 2) ? 0 : pbuf + 1;
    }

    // epilogue
    #pragma unroll
    for (int nt = 0; nt < 4; nt++) {
        const int n = n0 + wn + nt * 8 + (lane & 3) * 2;
        const float g0 = __ldg(&gamma[n]);
        const float g1 = __ldg(&gamma[n + 1]);
        const float b0 = bias ? __ldg(&bias[n])     : 0.f;
        const float b1 = bias ? __ldg(&bias[n + 1]) : 0.f;
        #pragma unroll
        for (int mt = 0; mt < 2; mt++) {
            const int r0 = m0 + wm + mt * 16 + (lane >> 2);
            float v00 = (acc[mt][nt][0] + b0) * g0;
            float v01 = (acc[mt][nt][1] + b1) * g1;
            float v10 = (acc[mt][nt][2] + b0) * g0;
            float v11 = (acc[mt][nt][3] + b1) * g1;
            if (HALF_OUT) {
                __half* C = (__half*)Cv;
                if (!GUARD || r0 < M)
                    *(uint32_t*)(C + (size_t)r0 * 320 + n) = f2h2(v00, v01);
                if (!GUARD || r0 + 8 < M)
                    *(uint32_t*)(C + (size_t)(r0 + 8) * 320 + n) = f2h2(v10, v11);
            } else {
                float* C = (float*)Cv;
                if (!GUARD || r0 < M) {
                    float2 p; p.x = v00; p.y = v01;
                    *(float2*)(C + (size_t)r0 * 320 + n) = p;
                }
                if (!GUARD || r0 + 8 < M) {
                    float2 p; p.x = v10; p.y = v11;
                    *(float2*)(C + (size_t)(r0 + 8) * 320 + n) = p;
                }
            }
        }
    }
}

// ---------------------------------------------------------------------------
// HMMA attention: per CTA 256 queries of one (b,h), 8 warps.  NK=77 -> 80.
//   V staged row-major via cp.async; PV B-fragments via ldmatrix.trans.
// ---------------------------------------------------------------------------
__global__ void __launch_bounds__(256)
attn_hmma(const __half* __restrict__ qh, const __half* __restrict__ kh,
          const __half* __restrict__ vh, __half* __restrict__ oh)
{
    __shared__ __half Qs[256][56];   // queries x dh(48 used)          28672 B
    __shared__ __half Ks[80][56];    // keys x dh                       8960 B
    __shared__ __half Vs[80][40];    // keys x dh (row-major)           6400 B

    const int b = blockIdx.z, h = blockIdx.y;
    const int tid = threadIdx.x, lane = tid & 31, wid = tid >> 5;
    const int m0 = blockIdx.x * 256;

    const __half* qbase = qh + ((size_t)b * NQ_ + m0) * INNER_ + h * DH_;
    const __half* kbase = kh + ((size_t)b * NK_) * INNER_ + h * DH_;
    const __half* vbase = vh + ((size_t)b * NK_) * INNER_ + h * DH_;

    // stage Q: 256 rows x 5 chunks = 1280
    #pragma unroll
    for (int i = 0; i < 5; i++) {
        int c = tid + i * 256;
        int r = c / 5, s = c % 5;
        cp16(smem_u32(&Qs[r][s * 8]), qbase + (size_t)r * INNER_ + s * 8);
    }
    // stage K: 77 rows x 5 = 385
    for (int c = tid; c < 385; c += 256) {
        int r = c / 5, s = c % 5;
        cp16(smem_u32(&Ks[r][s * 8]), kbase + (size_t)r * INNER_ + s * 8);
    }
    // stage V row-major: 385
    for (int c = tid; c < 385; c += 256) {
        int r = c / 5, s = c % 5;
        cp16(smem_u32(&Vs[r][s * 8]), vbase + (size_t)r * INNER_ + s * 8);
    }
    CP_COMMIT();

    // zero pads (disjoint from cp.async targets)
    const uint4 z4 = make_uint4(0, 0, 0, 0);
    *(uint4*)&Qs[tid][40] = z4;                       // Q dh pad 40-47
    if (tid < 80) *(uint4*)&Ks[tid][40] = z4;         // K dh pad
    if (tid < 15) {                                   // K key-pad rows 77-79
        int r = 77 + tid / 5, s = tid % 5;
        *(uint4*)&Ks[r][s * 8] = z4;
    }
    if (tid >= 32 && tid < 47) {                      // V key-pad rows 77-79
        int t = tid - 32;
        int r = 77 + t / 5, s = t % 5;
        *(uint4*)&Vs[r][s * 8] = z4;
    }
    CP_WAIT(0);
    __syncthreads();

    // --- S = Q K^T : warp = 32 queries (2 m16) x 80 keys ---
    const int wq = wid * 32;
    float w[2][10][4];
    #pragma unroll
    for (int mt = 0; mt < 2; mt++)
        #pragma unroll
        for (int nt = 0; nt < 10; nt++)
            #pragma unroll
            for (int i = 0; i < 4; i++) w[mt][nt][i] = 0.f;

    #pragma unroll
    for (int ksi = 0; ksi < 3; ksi++) {
        uint32_t af[2][4];
        #pragma unroll
        for (int mt = 0; mt < 2; mt++)
            ldm_x4(af[mt], smem_u32(&Qs[wq + mt * 16 + (lane & 15)]
                                       [ksi * 16 + ((lane >> 4) & 1) * 8]));
        #pragma unroll
        for (int nh = 0; nh < 5; nh++) {
            uint32_t bf[4];
            ldm_x4(bf, smem_u32(&Ks[nh * 16 + (lane & 7) + ((lane >> 4) << 3)]
                                   [ksi * 16 + ((lane >> 3) & 1) * 8]));
            #pragma unroll
            for (int mt = 0; mt < 2; mt++) {
                mma16816(w[mt][nh * 2],     af[mt], bf[0], bf[1]);
                mma16816(w[mt][nh * 2 + 1], af[mt], bf[2], bf[3]);
            }
        }
    }

    // --- softmax weights: w = exp(s*scale), mask j>=77, row sums ---
    const float scale = 0.15811388300841897f;   // 40^-0.5
    const int q2 = lane & 3;
    const bool ok0 = (72 + q2 * 2)     < 77;
    const bool ok1 = (72 + q2 * 2 + 1) < 77;
    float inv0[2], inv1[2];
    #pragma unroll
    for (int mt = 0; mt < 2; mt++) {
        float s0 = 0.f, s1 = 0.f;
        #pragma unroll
        for (int nt = 0; nt < 10; nt++) {
            float e0 = __expf(w[mt][nt][0] * scale);
            float e1 = __expf(w[mt][nt][1] * scale);
            float e2 = __expf(w[mt][nt][2] * scale);
            float e3 = __expf(w[mt][nt][3] * scale);
            if (nt == 9) {
                if (!ok0) { e0 = 0.f; e2 = 0.f; }
                if (!ok1) { e1 = 0.f; e3 = 0.f; }
            }
            w[mt][nt][0] = e0; w[mt][nt][1] = e1;
            w[mt][nt][2] = e2; w[mt][nt][3] = e3;
            s0 += e0 + e1;
            s1 += e2 + e3;
        }
        s0 += __shfl_xor_sync(0xffffffffu, s0, 1);
        s0 += __shfl_xor_sync(0xffffffffu, s0, 2);
        s1 += __shfl_xor_sync(0xffffffffu, s1, 1);
        s1 += __shfl_xor_sync(0xffffffffu, s1, 2);
        inv0[mt] = 1.f / s0;
        inv1[mt] = 1.f / s1;
    }

    // --- O = P V : trans-ldmatrix B fragments from row-major Vs ---
    float oacc[2][5][4];
    #pragma unroll
    for (int mt = 0; mt < 2; mt++)
        #pragma unroll
        for (int nt = 0; nt < 5; nt++)
            #pragma unroll
            for (int i = 0; i < 4; i++) oacc[mt][nt][i] = 0.f;

    #pragma unroll
    for (int kk = 0; kk < 5; kk++) {
        const int krow = kk * 16 + (lane & 7) + ((lane >> 3) & 1) * 8;
        uint32_t bA[4], bB[4], bC[2];
        ldm_x4t(bA, smem_u32(&Vs[krow][(lane >> 4) << 3]));
        ldm_x4t(bB, smem_u32(&Vs[krow][16 + ((lane >> 4) << 3)]));
        ldm_x2t(bC, smem_u32(&Vs[krow][32]));
        #pragma unroll
        for (int mt = 0; mt < 2; mt++) {
            uint32_t pa[4];
            pa[0] = f2h2(w[mt][2 * kk][0],     w[mt][2 * kk][1]);
            pa[1] = f2h2(w[mt][2 * kk][2],     w[mt][2 * kk][3]);
            pa[2] = f2h2(w[mt][2 * kk + 1][0], w[mt][2 * kk + 1][1]);
            pa[3] = f2h2(w[mt][2 * kk + 1][2], w[mt][2 * kk + 1][3]);
            mma16816(oacc[mt][0], pa, bA[0], bA[1]);
            mma16816(oacc[mt][1], pa, bA[2], bA[3]);
            mma16816(oacc[mt][2], pa, bB[0], bB[1]);
            mma16816(oacc[mt][3], pa, bB[2], bB[3]);
            mma16816(oacc[mt][4], pa, bC[0], bC[1]);
        }
    }

    // --- scale by 1/rowsum, store fp16 ---
    __half* obase = oh + ((size_t)b * NQ_ + m0) * INNER_ + h * DH_;
    #pragma unroll
    for (int mt = 0; mt < 2; mt++) {
        const int r0 = wq + mt * 16 + (lane >> 2);
        #pragma unroll
        for (int nt = 0; nt < 5; nt++) {
            const int col = nt * 8 + q2 * 2;
            *(uint32_t*)(obase + (size_t)r0 * INNER_ + col) =
                f2h2(oacc[mt][nt][0] * inv0[mt], oacc[mt][nt][1] * inv0[mt]);
            *(uint32_t*)(obase + (size_t)(r0 + 8) * INNER_ + col) =
                f2h2(oacc[mt][nt][2] * inv1[mt], oacc[mt][nt][3] * inv1[mt]);
        }
    }
}

// ---------------------------------------------------------------------------
// Launch
// ---------------------------------------------------------------------------
extern "C" void kernel_launch(void* const* d_in, const int* in_sizes, int n_in,
                              void* d_out, int out_size)
{
    (void)in_sizes; (void)n_in; (void)out_size;
    const float* x   = (const float*)d_in[0];
    const float* ctx = (const float*)d_in[1];
    const float* Wq  = (const float*)d_in[2];
    const float* Wk  = (const float*)d_in[3];
    const float* Wv  = (const float*)d_in[4];
    const float* Wo  = (const float*)d_in[5];
    const float* bo  = (const float*)d_in[6];
    const float* gq  = (const float*)d_in[7];
    const float* gk  = (const float*)d_in[8];
    const float* gv  = (const float*)d_in[9];
    const float* go  = (const float*)d_in[10];
    float* out = (float*)d_out;

    __half *xh, *ch, *qh, *oh, *kh, *vh, *wqh, *wkh, *wvh, *woh;
    cudaGetSymbolAddress((void**)&xh,  g_xh);
    cudaGetSymbolAddress((void**)&ch,  g_ch);
    cudaGetSymbolAddress((void**)&qh,  g_qh);
    cudaGetSymbolAddress((void**)&oh,  g_oh);
    cudaGetSymbolAddress((void**)&kh,  g_kh);
    cudaGetSymbolAddress((void**)&vh,  g_vh);
    cudaGetSymbolAddress((void**)&wqh, g_wqh);
    cudaGetSymbolAddress((void**)&wkh, g_wkh);
    cudaGetSymbolAddress((void**)&wvh, g_wvh);
    cudaGetSymbolAddress((void**)&woh, g_woh);

    const int Mq  = B_ * NQ_;   // 131072
    const int Mkv = B_ * NK_;   // 2464

    dim3 thr(256);
    dim3 grid_q (Mq / HBM, 320 / HBN);                   // (1024, 5)
    dim3 grid_kv((Mkv + HBM - 1) / HBM, 320 / HBN);      // (20, 5)
    dim3 grid_at(NQ_ / 256, HEADS_, B_);                 // (16, 8, 32)

    // fp32 -> fp16 conversions
    f2h_kernel<<<4096, 256>>>(x,   xh,  Mq * QDIM_ / 4);
    f2h_kernel<<<1024, 256>>>(ctx, ch,  Mkv * CDIM_ / 4);
    f2h_kernel<<<64,   256>>>(Wq,  wqh, INNER_ * QDIM_ / 4);
    f2h_kernel<<<128,  256>>>(Wk,  wkh, INNER_ * CDIM_ / 4);
    f2h_kernel<<<128,  256>>>(Wv,  wvh, INNER_ * CDIM_ / 4);
    f2h_kernel<<<64,   256>>>(Wo,  woh, QDIM_ * INNER_ / 4);

    // K/V projections (K=768, fp16 out, guarded M)
    gemm_hmma_t<24, true, true><<<grid_kv, thr>>>(ch, wkh, gk, nullptr, kh, Mkv);
    gemm_hmma_t<24, true, true><<<grid_kv, thr>>>(ch, wvh, gv, nullptr, vh, Mkv);

    // Q projection (K=320, fp16 out)
    gemm_hmma_t<10, true, false><<<grid_q, thr>>>(xh, wqh, gq, nullptr, qh, Mq);

    // attention (HMMA, fp16 in/out)
    attn_hmma<<<grid_at, thr>>>(qh, kh, vh, oh);

    // output projection (K=320, fp32 out, +bias, *gamma)
    gemm_hmma_t<10, false, false><<<grid_q, thr>>>(oh, woh, go, bo, out, Mq);
}